// round 11
// baseline (speedup 1.0000x reference)
#include <cuda_runtime.h>
#include <cstdint>

#define BB     256
#define TT     32
#define CNN    512
#define HWSQ   196      // 14*14
#define HID    8
#define NG     32       // 4*HID gates
#define VV     37
#define CHUNKS 8                // pooling CTAs per batch
#define CPB    (CNN/CHUNKS)     // 64 channels per CTA
#define PTHR   256
#define PWARP  (PTHR/32)        // 8
#define CPW    (CPB/PWARP)      // 8 channels per warp
#define UNR    4
#define TTHR   256
#define CAPROW ((TT-1)*VV)      // 1147 staged caption floats per batch

// fc_in partial dots: [b][chunk][v]
__device__ float g_x0p[BB * CHUNKS * VV];

__device__ __forceinline__ unsigned long long mk_policy_evict_last() {
    unsigned long long p;
    asm("createpolicy.fractional.L2::evict_last.b64 %0, 1.0;" : "=l"(p));
    return p;
}

__device__ __forceinline__ float4 ldg_el(const float4* p, unsigned long long pol) {
    float4 v;
    asm volatile("ld.global.nc.L2::cache_hint.v4.f32 {%0,%1,%2,%3}, [%4], %5;"
                 : "=f"(v.x), "=f"(v.y), "=f"(v.z), "=f"(v.w)
                 : "l"(p), "l"(pol));
    return v;
}

__device__ __forceinline__ float tanh_fast(float x) {
    float y;
    asm("tanh.approx.f32 %0, %1;" : "=f"(y) : "f"(x));
    return y;
}
__device__ __forceinline__ float sigmoid_fast(float x) {
    return fmaf(0.5f, tanh_fast(0.5f * x), 0.5f);
}

// ---------------------------------------------------------------------------
// Kernel A (r9 form): pooling + uniform fc_in partials. grid = 2048.
// ---------------------------------------------------------------------------
__global__ __launch_bounds__(PTHR, 6) void pool_kernel(
    const float* __restrict__ feat,     // [B, 512, 14, 14]
    const float* __restrict__ W_in)     // [37, 512]
{
    __shared__ float spool[CPB];        // 64 channel means

    const int b     = blockIdx.x >> 3;
    const int chunk = blockIdx.x & 7;
    const int warp  = threadIdx.x >> 5;
    const int lane  = threadIdx.x & 31;

    const unsigned long long pol = mk_policy_evict_last();
    const float4* base = reinterpret_cast<const float4*>(feat + (size_t)b * CNN * HWSQ);
    const int c0 = chunk * CPB + warp * CPW;

    #pragma unroll
    for (int cc = 0; cc < CPW; cc += UNR) {
        float4 a[UNR], q[UNR];
        #pragma unroll
        for (int u = 0; u < UNR; ++u) {
            const float4* p = base + (size_t)(c0 + cc + u) * 49;   // 196 floats
            a[u] = ldg_el(p + lane, pol);
            if (lane < 17) q[u] = ldg_el(p + lane + 32, pol);
        }
        float s[UNR];
        #pragma unroll
        for (int u = 0; u < UNR; ++u) {
            s[u] = a[u].x + a[u].y + a[u].z + a[u].w;
            if (lane < 17) s[u] += q[u].x + q[u].y + q[u].z + q[u].w;
        }
        #pragma unroll
        for (int o = 16; o > 0; o >>= 1) {
            #pragma unroll
            for (int u = 0; u < UNR; ++u)
                s[u] += __shfl_down_sync(0xffffffffu, s[u], o);
        }
        if (lane == 0) {
            #pragma unroll
            for (int u = 0; u < UNR; ++u)
                spool[warp * CPW + cc + u] = s[u] * (1.0f / 196.0f);
        }
    }
    __syncthreads();

    // fc_in partials: warp w handles v = w, w+8, ... (coalesced W_in reads)
    const float p1 = spool[lane];
    const float p2 = spool[lane + 32];
    for (int v = warp; v < VV; v += PWARP) {
        const float* wr = W_in + v * CNN + chunk * CPB;
        float s = p1 * wr[lane] + p2 * wr[lane + 32];
        #pragma unroll
        for (int o = 16; o > 0; o >>= 1)
            s += __shfl_down_sync(0xffffffffu, s, o);
        if (lane == 0)
            g_x0p[(b * CHUNKS + chunk) * VV + v] = s;
    }
}

// ---------------------------------------------------------------------------
// Kernel B: tail, 2 batches per CTA, grid = 128 (SINGLE wave), block = 256.
// Warps 0-3 = batch 2*bx, warps 4-7 = batch 2*bx+1. All data staged once.
// ---------------------------------------------------------------------------
__global__ __launch_bounds__(TTHR) void tail_kernel(
    const float* __restrict__ captions, // [B, T, V]
    const float* __restrict__ W_ih,     // [32, 37]
    const float* __restrict__ b_ih,     // [32]
    const float* __restrict__ W_hh,     // [32, 8]
    const float* __restrict__ b_hh,     // [32]
    const float* __restrict__ W_out,    // [37, 8]
    const float* __restrict__ b_in,     // [37]
    const float* __restrict__ b_out,    // [37]
    float* __restrict__ out)            // [B, T, V]
{
    // shared (both halves)
    __shared__ float sWih[NG * VV];
    __shared__ float sWhh[NG * 9];      // padded stride 9
    __shared__ float sWout[VV * 9];     // padded stride 9
    __shared__ float sb[NG];
    __shared__ float sbo[VV];
    __shared__ float sbin[VV];
    // per-half
    __shared__ float scap[2][CAPROW];
    __shared__ float sx0p[2][CHUNKS * VV];
    __shared__ float xs[2][VV];
    __shared__ float xproj[2][TT * NG];
    __shared__ float hbuf[2][TT * HID];
    __shared__ float logits[2][TT * VV];

    const int tid  = threadIdx.x;
    const int warp = tid >> 5;
    const int lane = tid & 31;
    const int half = warp >> 2;          // 0 or 1
    const int hw   = warp & 3;           // warp within half
    const int htid = tid & 127;          // thread within half
    const int b    = blockIdx.x * 2 + half;

    // ---- stage everything (one batched coalesced exposure) ----
    for (int i = tid; i < NG * VV; i += TTHR) sWih[i] = W_ih[i];
    for (int i = tid; i < NG * HID; i += TTHR) sWhh[(i >> 3) * 9 + (i & 7)] = W_hh[i];
    for (int i = tid; i < VV * HID; i += TTHR) sWout[(i / 8) * 9 + (i & 7)] = W_out[i];
    if (tid < NG) sb[tid]  = b_ih[tid] + b_hh[tid];
    if (tid < VV) sbo[tid] = b_out[tid];
    if (tid < VV) sbin[tid] = b_in[tid];
    for (int i = htid; i < CAPROW; i += 128)
        scap[half][i] = captions[(size_t)b * TT * VV + i];
    for (int i = htid; i < CHUNKS * VV; i += 128)
        sx0p[half][i] = g_x0p[b * CHUNKS * VV + i];
    __syncthreads();

    // ---- x0 = b_in + 8 chunk partials (fixed order) ----
    if (htid < VV) {
        float x = sbin[htid];
        #pragma unroll
        for (int c = 0; c < CHUNKS; ++c)
            x += sx0p[half][c * VV + htid];
        xs[half][htid] = x;
    }
    __syncthreads();

    // ---- xproj: warp handles t = hw, hw+4, ... ----
    for (int t = hw; t < TT; t += 4) {
        const float* x = (t == 0) ? xs[half] : &scap[half][(t - 1) * VV];
        float acc = sb[lane];
        const float* wrow = &sWih[lane * VV];
        #pragma unroll
        for (int k = 0; k < VV; ++k)
            acc = fmaf(x[k], wrow[k], acc);
        xproj[half][t * NG + lane] = acc;
    }
    __syncthreads();

    // ---- recurrence (warp hw==0 of each half) ----
    if (hw == 0) {
        float whh0 = sWhh[lane * 9 + 0], whh1 = sWhh[lane * 9 + 1];
        float whh2 = sWhh[lane * 9 + 2], whh3 = sWhh[lane * 9 + 3];
        float whh4 = sWhh[lane * 9 + 4], whh5 = sWhh[lane * 9 + 5];
        float whh6 = sWhh[lane * 9 + 6], whh7 = sWhh[lane * 9 + 7];

        float h0 = 0.f, h1 = 0.f, h2 = 0.f, h3 = 0.f;
        float h4 = 0.f, h5 = 0.f, h6 = 0.f, h7 = 0.f;
        float c = 0.f;
        const int j8 = lane & 7;

        #pragma unroll
        for (int t = 0; t < TT; ++t) {
            float ga = xproj[half][t * NG + lane];
            float gb = 0.0f;
            ga = fmaf(h0, whh0, ga);  gb = fmaf(h1, whh1, gb);
            ga = fmaf(h2, whh2, ga);  gb = fmaf(h3, whh3, gb);
            ga = fmaf(h4, whh4, ga);  gb = fmaf(h5, whh5, gb);
            ga = fmaf(h6, whh6, ga);  gb = fmaf(h7, whh7, gb);
            float gate = ga + gb;

            float gi = __shfl_sync(0xffffffffu, gate, j8);
            float gf = __shfl_sync(0xffffffffu, gate, j8 + 8);
            float gg = __shfl_sync(0xffffffffu, gate, j8 + 16);
            float go = __shfl_sync(0xffffffffu, gate, j8 + 24);

            float i_ = sigmoid_fast(gi);
            float f_ = sigmoid_fast(gf);
            float g_ = tanh_fast(gg);
            float o_ = sigmoid_fast(go);
            c = fmaf(f_, c, i_ * g_);
            float hn = o_ * tanh_fast(c);

            h0 = __shfl_sync(0xffffffffu, hn, 0);
            h1 = __shfl_sync(0xffffffffu, hn, 1);
            h2 = __shfl_sync(0xffffffffu, hn, 2);
            h3 = __shfl_sync(0xffffffffu, hn, 3);
            h4 = __shfl_sync(0xffffffffu, hn, 4);
            h5 = __shfl_sync(0xffffffffu, hn, 5);
            h6 = __shfl_sync(0xffffffffu, hn, 6);
            h7 = __shfl_sync(0xffffffffu, hn, 7);

            if (lane < HID) hbuf[half][t * HID + lane] = hn;
        }
    }
    __syncthreads();

    // ---- fc_out: warp handles t = hw, hw+4, ... (all smem) ----
    for (int t = hw; t < TT; t += 4) {
        float acc1 = sbo[lane];
        float acc2 = (lane < VV - 32) ? sbo[32 + lane] : 0.0f;
        #pragma unroll
        for (int j = 0; j < HID; ++j) {
            float hv = hbuf[half][t * HID + j];
            acc1 = fmaf(hv, sWout[lane * 9 + j], acc1);
            if (lane < VV - 32)
                acc2 = fmaf(hv, sWout[(32 + lane) * 9 + j], acc2);
        }
        logits[half][t * VV + lane] = acc1;
        if (lane < VV - 32) logits[half][t * VV + 32 + lane] = acc2;
    }
    __syncthreads();

    // ---- softmax over TIME axis (per half: thread v owns column v) ----
    if (htid < VV) {
        float m = -1e30f;
        #pragma unroll
        for (int t = 0; t < TT; ++t)
            m = fmaxf(m, logits[half][t * VV + htid]);
        float s = 0.0f;
        #pragma unroll
        for (int t = 0; t < TT; ++t) {
            float e = __expf(logits[half][t * VV + htid] - m);
            s += e;
            logits[half][t * VV + htid] = e;
        }
        float r = 1.0f / s;
        #pragma unroll
        for (int t = 0; t < TT; ++t)
            logits[half][t * VV + htid] *= r;
    }
    __syncthreads();

    // ---- coalesced store (each half stores its batch) ----
    float* ob = out + (size_t)b * TT * VV;
    for (int i = htid; i < TT * VV; i += 128)
        ob[i] = logits[half][i];
}

// ---------------------------------------------------------------------------
extern "C" void kernel_launch(void* const* d_in, const int* in_sizes, int n_in,
                              void* d_out, int out_size)
{
    const float* features = (const float*)d_in[0];
    const float* captions = (const float*)d_in[1];
    const float* W_ih     = (const float*)d_in[2];
    const float* b_ih     = (const float*)d_in[3];
    const float* W_hh     = (const float*)d_in[4];
    const float* b_hh     = (const float*)d_in[5];
    const float* W_in     = (const float*)d_in[6];
    const float* b_in     = (const float*)d_in[7];
    const float* W_out    = (const float*)d_in[8];
    const float* b_out    = (const float*)d_in[9];
    float* out = (float*)d_out;

    pool_kernel<<<BB * CHUNKS, PTHR>>>(features, W_in);
    tail_kernel<<<BB / 2, TTHR>>>(captions, W_ih, b_ih, W_hh, b_hh,
                                  W_out, b_in, b_out, out);
    (void)in_sizes; (void)n_in; (void)out_size;
}

// round 12
// speedup vs baseline: 1.8131x; 1.8131x over previous
#include <cuda_runtime.h>
#include <cstdint>

#define BB   256
#define TT   32
#define CNN  512
#define HWSQ 196      // 14*14
#define HID  8
#define NG   32       // 4*HID gates
#define VV   37
#define NTHR 512
#define NWARP (NTHR/32)
#define CPW  (CNN/NWARP)   // 32 channels per warp
#define UNR  4             // channels reduced per batch of loads

__device__ __forceinline__ unsigned long long mk_policy_evict_last() {
    unsigned long long p;
    asm("createpolicy.fractional.L2::evict_last.b64 %0, 1.0;" : "=l"(p));
    return p;
}

__device__ __forceinline__ float4 ldg_el(const float4* p, unsigned long long pol) {
    float4 v;
    asm volatile("ld.global.nc.L2::cache_hint.v4.f32 {%0,%1,%2,%3}, [%4], %5;"
                 : "=f"(v.x), "=f"(v.y), "=f"(v.z), "=f"(v.w)
                 : "l"(p), "l"(pol));
    return v;
}

__device__ __forceinline__ float tanh_fast(float x) {
    float y;
    asm("tanh.approx.f32 %0, %1;" : "=f"(y) : "f"(x));
    return y;
}
__device__ __forceinline__ float sigmoid_fast(float x) {
    return fmaf(0.5f, tanh_fast(0.5f * x), 0.5f);
}

// ---------------------------------------------------------------------------
// One fully fused kernel (r3 structure). grid = B (256), block = 512.
// Phase 1: pool (evict_last policy loads, 4-channel unroll)
// Phase 2: fc_in -> x0
// Phase 3: xproj[t][gate]
// Phase 4: warp 0 recurrence (tanh.approx)
// Phase 5: fc_out + time-softmax + store
// ---------------------------------------------------------------------------
__global__ __launch_bounds__(NTHR) void lstm_fused_kernel(
    const float* __restrict__ feat,     // [B, 512, 14, 14]
    const float* __restrict__ captions, // [B, T, V]
    const float* __restrict__ W_ih,     // [32, 37]
    const float* __restrict__ b_ih,     // [32]
    const float* __restrict__ W_hh,     // [32, 8]
    const float* __restrict__ b_hh,     // [32]
    const float* __restrict__ W_in,     // [37, 512]
    const float* __restrict__ b_in,     // [37]
    const float* __restrict__ W_out,    // [37, 8]
    const float* __restrict__ b_out,    // [37]
    float* __restrict__ out)            // [B, T, V]
{
    __shared__ float pooled[CNN];
    __shared__ float xs[VV];
    __shared__ float sWih[NG * VV];
    __shared__ float sb[NG];
    __shared__ float xproj[TT * NG];
    __shared__ float hbuf[TT * HID];
    __shared__ float logits[TT * VV];

    const int b    = blockIdx.x;
    const int tid  = threadIdx.x;
    const int warp = tid >> 5;
    const int lane = tid & 31;

    // ---- stage small weights ----
    for (int i = tid; i < NG * VV; i += NTHR) sWih[i] = W_ih[i];
    if (tid < NG) sb[tid] = b_ih[tid] + b_hh[tid];

    // ---- Phase 1: adaptive avg pool (warp owns 32 contiguous channels) ----
    const unsigned long long pol = mk_policy_evict_last();
    const float4* base = reinterpret_cast<const float4*>(feat + (size_t)b * CNN * HWSQ);
    const int c0 = warp * CPW;
    #pragma unroll
    for (int cc = 0; cc < CPW; cc += UNR) {
        float4 a[UNR], q[UNR];
        #pragma unroll
        for (int u = 0; u < UNR; ++u) {
            const float4* p = base + (size_t)(c0 + cc + u) * 49;   // 196 floats
            a[u] = ldg_el(p + lane, pol);
            if (lane < 17) q[u] = ldg_el(p + lane + 32, pol);
        }
        float s[UNR];
        #pragma unroll
        for (int u = 0; u < UNR; ++u) {
            s[u] = a[u].x + a[u].y + a[u].z + a[u].w;
            if (lane < 17) s[u] += q[u].x + q[u].y + q[u].z + q[u].w;
        }
        #pragma unroll
        for (int o = 16; o > 0; o >>= 1) {
            #pragma unroll
            for (int u = 0; u < UNR; ++u)
                s[u] += __shfl_down_sync(0xffffffffu, s[u], o);
        }
        if (lane == 0) {
            #pragma unroll
            for (int u = 0; u < UNR; ++u)
                pooled[c0 + cc + u] = s[u] * (1.0f / 196.0f);
        }
    }
    __syncthreads();

    // ---- Phase 2: fc_in, warp-per-output ----
    for (int v = warp; v < VV; v += NWARP) {
        const float* w = W_in + v * CNN;
        float s = 0.0f;
        #pragma unroll 4
        for (int k = lane; k < CNN; k += 32)
            s += pooled[k] * w[k];
        #pragma unroll
        for (int o = 16; o > 0; o >>= 1)
            s += __shfl_down_sync(0xffffffffu, s, o);
        if (lane == 0) xs[v] = s + b_in[v];
    }
    __syncthreads();

    // ---- Phase 3: xproj (warp w handles t = w, w+16) ----
    for (int t = warp; t < TT; t += NWARP) {
        const float* x = (t == 0) ? xs : (captions + ((size_t)b * TT + (t - 1)) * VV);
        float acc = sb[lane];
        const float* wrow = &sWih[lane * VV];
        #pragma unroll
        for (int k = 0; k < VV; ++k)
            acc = fmaf(x[k], wrow[k], acc);
        xproj[t * NG + lane] = acc;
    }
    __syncthreads();

    // ---- Phase 4: recurrence (warp 0 only) ----
    if (warp == 0) {
        const float4* w4 = reinterpret_cast<const float4*>(W_hh);
        float4 wa = w4[lane * 2];
        float4 wb = w4[lane * 2 + 1];
        float whh0 = wa.x, whh1 = wa.y, whh2 = wa.z, whh3 = wa.w;
        float whh4 = wb.x, whh5 = wb.y, whh6 = wb.z, whh7 = wb.w;

        float h0 = 0.f, h1 = 0.f, h2 = 0.f, h3 = 0.f;
        float h4 = 0.f, h5 = 0.f, h6 = 0.f, h7 = 0.f;
        float c = 0.f;
        const int j8 = lane & 7;

        #pragma unroll
        for (int t = 0; t < TT; ++t) {
            float ga = xproj[t * NG + lane];
            float gb = 0.0f;
            ga = fmaf(h0, whh0, ga);  gb = fmaf(h1, whh1, gb);
            ga = fmaf(h2, whh2, ga);  gb = fmaf(h3, whh3, gb);
            ga = fmaf(h4, whh4, ga);  gb = fmaf(h5, whh5, gb);
            ga = fmaf(h6, whh6, ga);  gb = fmaf(h7, whh7, gb);
            float gate = ga + gb;

            float gi = __shfl_sync(0xffffffffu, gate, j8);
            float gf = __shfl_sync(0xffffffffu, gate, j8 + 8);
            float gg = __shfl_sync(0xffffffffu, gate, j8 + 16);
            float go = __shfl_sync(0xffffffffu, gate, j8 + 24);

            float i_ = sigmoid_fast(gi);
            float f_ = sigmoid_fast(gf);
            float g_ = tanh_fast(gg);
            float o_ = sigmoid_fast(go);
            c = fmaf(f_, c, i_ * g_);
            float hn = o_ * tanh_fast(c);

            h0 = __shfl_sync(0xffffffffu, hn, 0);
            h1 = __shfl_sync(0xffffffffu, hn, 1);
            h2 = __shfl_sync(0xffffffffu, hn, 2);
            h3 = __shfl_sync(0xffffffffu, hn, 3);
            h4 = __shfl_sync(0xffffffffu, hn, 4);
            h5 = __shfl_sync(0xffffffffu, hn, 5);
            h6 = __shfl_sync(0xffffffffu, hn, 6);
            h7 = __shfl_sync(0xffffffffu, hn, 7);

            if (lane < HID) hbuf[t * HID + lane] = hn;
        }
    }
    __syncthreads();

    // ---- Phase 5a: fc_out, warp w handles t = w, w+16 ----
    for (int t = warp; t < TT; t += NWARP) {
        float acc1 = b_out[lane];
        float acc2 = (lane < VV - 32) ? b_out[32 + lane] : 0.0f;
        #pragma unroll
        for (int j = 0; j < HID; ++j) {
            float hv = hbuf[t * HID + j];
            acc1 = fmaf(hv, W_out[lane * HID + j], acc1);
            if (lane < VV - 32)
                acc2 = fmaf(hv, W_out[(32 + lane) * HID + j], acc2);
        }
        logits[t * VV + lane] = acc1;
        if (lane < VV - 32) logits[t * VV + 32 + lane] = acc2;
    }
    __syncthreads();

    // ---- Phase 5b: softmax over TIME axis ----
    if (tid < VV) {
        float m = -1e30f;
        #pragma unroll
        for (int t = 0; t < TT; ++t)
            m = fmaxf(m, logits[t * VV + tid]);
        float s = 0.0f;
        #pragma unroll
        for (int t = 0; t < TT; ++t) {
            float e = __expf(logits[t * VV + tid] - m);
            s += e;
            logits[t * VV + tid] = e;
        }
        float r = 1.0f / s;
        #pragma unroll
        for (int t = 0; t < TT; ++t)
            logits[t * VV + tid] *= r;
    }
    __syncthreads();

    // ---- Phase 5c: coalesced store ----
    float* ob = out + (size_t)b * TT * VV;
    for (int i = tid; i < TT * VV; i += NTHR)
        ob[i] = logits[i];
}

// ---------------------------------------------------------------------------
extern "C" void kernel_launch(void* const* d_in, const int* in_sizes, int n_in,
                              void* d_out, int out_size)
{
    const float* features = (const float*)d_in[0];
    const float* captions = (const float*)d_in[1];
    const float* W_ih     = (const float*)d_in[2];
    const float* b_ih     = (const float*)d_in[3];
    const float* W_hh     = (const float*)d_in[4];
    const float* b_hh     = (const float*)d_in[5];
    const float* W_in     = (const float*)d_in[6];
    const float* b_in     = (const float*)d_in[7];
    const float* W_out    = (const float*)d_in[8];
    const float* b_out    = (const float*)d_in[9];
    float* out = (float*)d_out;

    lstm_fused_kernel<<<BB, NTHR>>>(features, captions, W_ih, b_ih, W_hh, b_hh,
                                    W_in, b_in, W_out, b_out, out);
    (void)in_sizes; (void)n_in; (void)out_size;
}

// round 13
// speedup vs baseline: 1.9621x; 1.0822x over previous
#include <cuda_runtime.h>
#include <cstdint>

#define BB   256
#define TT   32
#define CNN  512
#define HWSQ 196      // 14*14
#define HID  8
#define NG   32       // 4*HID gates
#define VV   37
#define NTHR 512
#define NWARP (NTHR/32)
#define CPW  (CNN/NWARP)   // 32 channels per warp
#define UNR  4             // channels reduced per batch of loads

__device__ __forceinline__ unsigned long long mk_policy_evict_last() {
    unsigned long long p;
    asm("createpolicy.fractional.L2::evict_last.b64 %0, 1.0;" : "=l"(p));
    return p;
}

__device__ __forceinline__ float4 ldg_el(const float4* p, unsigned long long pol) {
    float4 v;
    asm volatile("ld.global.nc.L2::cache_hint.v4.f32 {%0,%1,%2,%3}, [%4], %5;"
                 : "=f"(v.x), "=f"(v.y), "=f"(v.z), "=f"(v.w)
                 : "l"(p), "l"(pol));
    return v;
}

__device__ __forceinline__ float tanh_fast(float x) {
    float y;
    asm("tanh.approx.f32 %0, %1;" : "=f"(y) : "f"(x));
    return y;
}
__device__ __forceinline__ float sigmoid_fast(float x) {
    return fmaf(0.5f, tanh_fast(0.5f * x), 0.5f);
}

// ---------------------------------------------------------------------------
// Fully fused kernel (r12 base). grid = B (256), block = 512.
// r13 deltas: pipelined xproj prefetch in recurrence; 8-lane-subgroup
// parallel time-softmax with fused normalized store.
// ---------------------------------------------------------------------------
__global__ __launch_bounds__(NTHR) void lstm_fused_kernel(
    const float* __restrict__ feat,     // [B, 512, 14, 14]
    const float* __restrict__ captions, // [B, T, V]
    const float* __restrict__ W_ih,     // [32, 37]
    const float* __restrict__ b_ih,     // [32]
    const float* __restrict__ W_hh,     // [32, 8]
    const float* __restrict__ b_hh,     // [32]
    const float* __restrict__ W_in,     // [37, 512]
    const float* __restrict__ b_in,     // [37]
    const float* __restrict__ W_out,    // [37, 8]
    const float* __restrict__ b_out,    // [37]
    float* __restrict__ out)            // [B, T, V]
{
    __shared__ float pooled[CNN];
    __shared__ float xs[VV];
    __shared__ float sWih[NG * VV];
    __shared__ float sb[NG];
    __shared__ float xproj[TT * NG];
    __shared__ float hbuf[TT * HID];
    __shared__ float logits[TT * VV];

    const int b    = blockIdx.x;
    const int tid  = threadIdx.x;
    const int warp = tid >> 5;
    const int lane = tid & 31;

    // ---- stage small weights ----
    for (int i = tid; i < NG * VV; i += NTHR) sWih[i] = W_ih[i];
    if (tid < NG) sb[tid] = b_ih[tid] + b_hh[tid];

    // ---- Phase 1: adaptive avg pool (warp owns 32 contiguous channels) ----
    const unsigned long long pol = mk_policy_evict_last();
    const float4* base = reinterpret_cast<const float4*>(feat + (size_t)b * CNN * HWSQ);
    const int c0 = warp * CPW;
    #pragma unroll
    for (int cc = 0; cc < CPW; cc += UNR) {
        float4 a[UNR], q[UNR];
        #pragma unroll
        for (int u = 0; u < UNR; ++u) {
            const float4* p = base + (size_t)(c0 + cc + u) * 49;   // 196 floats
            a[u] = ldg_el(p + lane, pol);
            if (lane < 17) q[u] = ldg_el(p + lane + 32, pol);
        }
        float s[UNR];
        #pragma unroll
        for (int u = 0; u < UNR; ++u) {
            s[u] = a[u].x + a[u].y + a[u].z + a[u].w;
            if (lane < 17) s[u] += q[u].x + q[u].y + q[u].z + q[u].w;
        }
        #pragma unroll
        for (int o = 16; o > 0; o >>= 1) {
            #pragma unroll
            for (int u = 0; u < UNR; ++u)
                s[u] += __shfl_down_sync(0xffffffffu, s[u], o);
        }
        if (lane == 0) {
            #pragma unroll
            for (int u = 0; u < UNR; ++u)
                pooled[c0 + cc + u] = s[u] * (1.0f / 196.0f);
        }
    }
    __syncthreads();

    // ---- Phase 2: fc_in, warp-per-output ----
    for (int v = warp; v < VV; v += NWARP) {
        const float* w = W_in + v * CNN;
        float s = 0.0f;
        #pragma unroll 4
        for (int k = lane; k < CNN; k += 32)
            s += pooled[k] * w[k];
        #pragma unroll
        for (int o = 16; o > 0; o >>= 1)
            s += __shfl_down_sync(0xffffffffu, s, o);
        if (lane == 0) xs[v] = s + b_in[v];
    }
    __syncthreads();

    // ---- Phase 3: xproj (warp w handles t = w, w+16) ----
    for (int t = warp; t < TT; t += NWARP) {
        const float* x = (t == 0) ? xs : (captions + ((size_t)b * TT + (t - 1)) * VV);
        float acc = sb[lane];
        const float* wrow = &sWih[lane * VV];
        #pragma unroll
        for (int k = 0; k < VV; ++k)
            acc = fmaf(x[k], wrow[k], acc);
        xproj[t * NG + lane] = acc;
    }
    __syncthreads();

    // ---- Phase 4: recurrence (warp 0 only, pipelined xproj prefetch) ----
    if (warp == 0) {
        const float4* w4 = reinterpret_cast<const float4*>(W_hh);
        float4 wa = w4[lane * 2];
        float4 wb = w4[lane * 2 + 1];
        float whh0 = wa.x, whh1 = wa.y, whh2 = wa.z, whh3 = wa.w;
        float whh4 = wb.x, whh5 = wb.y, whh6 = wb.z, whh7 = wb.w;

        float h0 = 0.f, h1 = 0.f, h2 = 0.f, h3 = 0.f;
        float h4 = 0.f, h5 = 0.f, h6 = 0.f, h7 = 0.f;
        float c = 0.f;
        const int j8 = lane & 7;

        float xp = xproj[lane];              // t = 0 row
        #pragma unroll
        for (int t = 0; t < TT; ++t) {
            // prefetch next row first: LDS latency hides under this step
            float xpn = (t < TT - 1) ? xproj[(t + 1) * NG + lane] : 0.0f;

            float ga = xp;
            float gb = 0.0f;
            ga = fmaf(h0, whh0, ga);  gb = fmaf(h1, whh1, gb);
            ga = fmaf(h2, whh2, ga);  gb = fmaf(h3, whh3, gb);
            ga = fmaf(h4, whh4, ga);  gb = fmaf(h5, whh5, gb);
            ga = fmaf(h6, whh6, ga);  gb = fmaf(h7, whh7, gb);
            float gate = ga + gb;

            float gi = __shfl_sync(0xffffffffu, gate, j8);
            float gf = __shfl_sync(0xffffffffu, gate, j8 + 8);
            float gg = __shfl_sync(0xffffffffu, gate, j8 + 16);
            float go = __shfl_sync(0xffffffffu, gate, j8 + 24);

            float i_ = sigmoid_fast(gi);
            float f_ = sigmoid_fast(gf);
            float g_ = tanh_fast(gg);
            float o_ = sigmoid_fast(go);
            c = fmaf(f_, c, i_ * g_);
            float hn = o_ * tanh_fast(c);

            h0 = __shfl_sync(0xffffffffu, hn, 0);
            h1 = __shfl_sync(0xffffffffu, hn, 1);
            h2 = __shfl_sync(0xffffffffu, hn, 2);
            h3 = __shfl_sync(0xffffffffu, hn, 3);
            h4 = __shfl_sync(0xffffffffu, hn, 4);
            h5 = __shfl_sync(0xffffffffu, hn, 5);
            h6 = __shfl_sync(0xffffffffu, hn, 6);
            h7 = __shfl_sync(0xffffffffu, hn, 7);

            if (lane < HID) hbuf[t * HID + lane] = hn;
            xp = xpn;
        }
    }
    __syncthreads();

    // ---- Phase 5a: fc_out, warp w handles t = w, w+16 ----
    for (int t = warp; t < TT; t += NWARP) {
        float acc1 = b_out[lane];
        float acc2 = (lane < VV - 32) ? b_out[32 + lane] : 0.0f;
        #pragma unroll
        for (int j = 0; j < HID; ++j) {
            float hv = hbuf[t * HID + j];
            acc1 = fmaf(hv, W_out[lane * HID + j], acc1);
            if (lane < VV - 32)
                acc2 = fmaf(hv, W_out[(32 + lane) * HID + j], acc2);
        }
        logits[t * VV + lane] = acc1;
        if (lane < VV - 32) logits[t * VV + 32 + lane] = acc2;
    }
    __syncthreads();

    // ---- Phase 5b: parallel softmax over TIME + fused store ----
    // 8-lane subgroup per column: warp w, subgroup sg -> column v = w*4+sg.
    {
        const int sg = lane >> 3;            // 0..3
        const int sl = lane & 7;             // 0..7 -> t = sl, sl+8, sl+16, sl+24
        const int v  = warp * 4 + sg;        // 0..63; valid if < VV
        const int vc = (v < VV) ? v : 0;     // clamped for safe smem reads

        float x0 = logits[(sl     ) * VV + vc];
        float x1 = logits[(sl +  8) * VV + vc];
        float x2 = logits[(sl + 16) * VV + vc];
        float x3 = logits[(sl + 24) * VV + vc];

        float m = fmaxf(fmaxf(x0, x1), fmaxf(x2, x3));
        #pragma unroll
        for (int o = 4; o > 0; o >>= 1)
            m = fmaxf(m, __shfl_xor_sync(0xffffffffu, m, o, 8));

        float e0 = __expf(x0 - m);
        float e1 = __expf(x1 - m);
        float e2 = __expf(x2 - m);
        float e3 = __expf(x3 - m);
        float s = (e0 + e1) + (e2 + e3);
        #pragma unroll
        for (int o = 4; o > 0; o >>= 1)
            s += __shfl_xor_sync(0xffffffffu, s, o, 8);
        float r = 1.0f / s;

        if (v < VV) {
            float* ob = out + (size_t)b * TT * VV + v;
            ob[(sl     ) * VV] = e0 * r;
            ob[(sl +  8) * VV] = e1 * r;
            ob[(sl + 16) * VV] = e2 * r;
            ob[(sl + 24) * VV] = e3 * r;
        }
    }
}

// ---------------------------------------------------------------------------
extern "C" void kernel_launch(void* const* d_in, const int* in_sizes, int n_in,
                              void* d_out, int out_size)
{
    const float* features = (const float*)d_in[0];
    const float* captions = (const float*)d_in[1];
    const float* W_ih     = (const float*)d_in[2];
    const float* b_ih     = (const float*)d_in[3];
    const float* W_hh     = (const float*)d_in[4];
    const float* b_hh     = (const float*)d_in[5];
    const float* W_in     = (const float*)d_in[6];
    const float* b_in     = (const float*)d_in[7];
    const float* W_out    = (const float*)d_in[8];
    const float* b_out    = (const float*)d_in[9];
    float* out = (float*)d_out;

    lstm_fused_kernel<<<BB, NTHR>>>(features, captions, W_ih, b_ih, W_hh, b_hh,
                                    W_in, b_in, W_out, b_out, out);
    (void)in_sizes; (void)n_in; (void)out_size;
}

// round 14
// speedup vs baseline: 2.1526x; 1.0971x over previous
#include <cuda_runtime.h>
#include <cstdint>

#define BB   256
#define TT   32
#define CNN  512
#define HWSQ 196      // 14*14
#define HID  8
#define NG   32       // 4*HID gates
#define VV   37
#define NTHR 512
#define NWARP (NTHR/32)
#define CPW  (CNN/NWARP)   // 32 channels per warp
#define UNR  4             // channels reduced per batch of loads
#define CAPROW ((TT-1)*VV) // 1147 caption floats per batch

__device__ __forceinline__ unsigned long long mk_policy_evict_last() {
    unsigned long long p;
    asm("createpolicy.fractional.L2::evict_last.b64 %0, 1.0;" : "=l"(p));
    return p;
}

__device__ __forceinline__ float4 ldg_el(const float4* p, unsigned long long pol) {
    float4 v;
    asm volatile("ld.global.nc.L2::cache_hint.v4.f32 {%0,%1,%2,%3}, [%4], %5;"
                 : "=f"(v.x), "=f"(v.y), "=f"(v.z), "=f"(v.w)
                 : "l"(p), "l"(pol));
    return v;
}

__device__ __forceinline__ float tanh_fast(float x) {
    float y;
    asm("tanh.approx.f32 %0, %1;" : "=f"(y) : "f"(x));
    return y;
}
__device__ __forceinline__ float sigmoid_fast(float x) {
    return fmaf(0.5f, tanh_fast(0.5f * x), 0.5f);
}

// ---------------------------------------------------------------------------
// Fully fused kernel. grid = B (256), block = 512.
// r14 deltas: ALL small globals (W_ih, W_out, b's, captions) staged into smem
// at kernel start -> loads complete under the pooling stream; phases 3/5a are
// pure smem afterwards. Recurrence pipelined; softmax 8-lane parallel.
// ---------------------------------------------------------------------------
__global__ __launch_bounds__(NTHR) void lstm_fused_kernel(
    const float* __restrict__ feat,     // [B, 512, 14, 14]
    const float* __restrict__ captions, // [B, T, V]
    const float* __restrict__ W_ih,     // [32, 37]
    const float* __restrict__ b_ih,     // [32]
    const float* __restrict__ W_hh,     // [32, 8]
    const float* __restrict__ b_hh,     // [32]
    const float* __restrict__ W_in,     // [37, 512]
    const float* __restrict__ b_in,     // [37]
    const float* __restrict__ W_out,    // [37, 8]
    const float* __restrict__ b_out,    // [37]
    float* __restrict__ out)            // [B, T, V]
{
    __shared__ float pooled[CNN];
    __shared__ float xs[VV];
    __shared__ float sWih[NG * VV];
    __shared__ float sWout[VV * 9];     // padded stride 9
    __shared__ float sb[NG];
    __shared__ float sbo[VV];
    __shared__ float scap[CAPROW];
    __shared__ float xproj[TT * NG];
    __shared__ float hbuf[TT * HID];
    __shared__ float logits[TT * VV];

    const int b    = blockIdx.x;
    const int tid  = threadIdx.x;
    const int warp = tid >> 5;
    const int lane = tid & 31;

    // ---- stage ALL small globals up front (completes under pooling) ----
    for (int i = tid; i < NG * VV; i += NTHR) sWih[i] = W_ih[i];
    for (int i = tid; i < VV * HID; i += NTHR) sWout[(i / 8) * 9 + (i & 7)] = W_out[i];
    for (int i = tid; i < CAPROW; i += NTHR) scap[i] = captions[(size_t)b * TT * VV + i];
    if (tid < NG) sb[tid]  = b_ih[tid] + b_hh[tid];
    if (tid < VV) sbo[tid] = b_out[tid];

    // ---- Phase 1: adaptive avg pool (warp owns 32 contiguous channels) ----
    const unsigned long long pol = mk_policy_evict_last();
    const float4* base = reinterpret_cast<const float4*>(feat + (size_t)b * CNN * HWSQ);
    const int c0 = warp * CPW;
    #pragma unroll
    for (int cc = 0; cc < CPW; cc += UNR) {
        float4 a[UNR], q[UNR];
        #pragma unroll
        for (int u = 0; u < UNR; ++u) {
            const float4* p = base + (size_t)(c0 + cc + u) * 49;   // 196 floats
            a[u] = ldg_el(p + lane, pol);
            if (lane < 17) q[u] = ldg_el(p + lane + 32, pol);
        }
        float s[UNR];
        #pragma unroll
        for (int u = 0; u < UNR; ++u) {
            s[u] = a[u].x + a[u].y + a[u].z + a[u].w;
            if (lane < 17) s[u] += q[u].x + q[u].y + q[u].z + q[u].w;
        }
        #pragma unroll
        for (int o = 16; o > 0; o >>= 1) {
            #pragma unroll
            for (int u = 0; u < UNR; ++u)
                s[u] += __shfl_down_sync(0xffffffffu, s[u], o);
        }
        if (lane == 0) {
            #pragma unroll
            for (int u = 0; u < UNR; ++u)
                pooled[c0 + cc + u] = s[u] * (1.0f / 196.0f);
        }
    }
    __syncthreads();

    // ---- Phase 2: fc_in, warp-per-output ----
    for (int v = warp; v < VV; v += NWARP) {
        const float* w = W_in + v * CNN;
        float s = 0.0f;
        #pragma unroll 4
        for (int k = lane; k < CNN; k += 32)
            s += pooled[k] * w[k];
        #pragma unroll
        for (int o = 16; o > 0; o >>= 1)
            s += __shfl_down_sync(0xffffffffu, s, o);
        if (lane == 0) xs[v] = s + b_in[v];
    }
    __syncthreads();

    // ---- Phase 3: xproj (warp w handles t = w, w+16) — pure smem ----
    for (int t = warp; t < TT; t += NWARP) {
        const float* x = (t == 0) ? xs : &scap[(t - 1) * VV];
        float acc = sb[lane];
        const float* wrow = &sWih[lane * VV];
        #pragma unroll
        for (int k = 0; k < VV; ++k)
            acc = fmaf(x[k], wrow[k], acc);
        xproj[t * NG + lane] = acc;
    }
    __syncthreads();

    // ---- Phase 4: recurrence (warp 0 only, pipelined xproj prefetch) ----
    if (warp == 0) {
        const float4* w4 = reinterpret_cast<const float4*>(W_hh);
        float4 wa = w4[lane * 2];
        float4 wb = w4[lane * 2 + 1];
        float whh0 = wa.x, whh1 = wa.y, whh2 = wa.z, whh3 = wa.w;
        float whh4 = wb.x, whh5 = wb.y, whh6 = wb.z, whh7 = wb.w;

        float h0 = 0.f, h1 = 0.f, h2 = 0.f, h3 = 0.f;
        float h4 = 0.f, h5 = 0.f, h6 = 0.f, h7 = 0.f;
        float c = 0.f;
        const int j8 = lane & 7;

        float xp = xproj[lane];              // t = 0 row
        #pragma unroll
        for (int t = 0; t < TT; ++t) {
            float xpn = (t < TT - 1) ? xproj[(t + 1) * NG + lane] : 0.0f;

            float ga = xp;
            float gb = 0.0f;
            ga = fmaf(h0, whh0, ga);  gb = fmaf(h1, whh1, gb);
            ga = fmaf(h2, whh2, ga);  gb = fmaf(h3, whh3, gb);
            ga = fmaf(h4, whh4, ga);  gb = fmaf(h5, whh5, gb);
            ga = fmaf(h6, whh6, ga);  gb = fmaf(h7, whh7, gb);
            float gate = ga + gb;

            float gi = __shfl_sync(0xffffffffu, gate, j8);
            float gf = __shfl_sync(0xffffffffu, gate, j8 + 8);
            float gg = __shfl_sync(0xffffffffu, gate, j8 + 16);
            float go = __shfl_sync(0xffffffffu, gate, j8 + 24);

            float i_ = sigmoid_fast(gi);
            float f_ = sigmoid_fast(gf);
            float g_ = tanh_fast(gg);
            float o_ = sigmoid_fast(go);
            c = fmaf(f_, c, i_ * g_);
            float hn = o_ * tanh_fast(c);

            h0 = __shfl_sync(0xffffffffu, hn, 0);
            h1 = __shfl_sync(0xffffffffu, hn, 1);
            h2 = __shfl_sync(0xffffffffu, hn, 2);
            h3 = __shfl_sync(0xffffffffu, hn, 3);
            h4 = __shfl_sync(0xffffffffu, hn, 4);
            h5 = __shfl_sync(0xffffffffu, hn, 5);
            h6 = __shfl_sync(0xffffffffu, hn, 6);
            h7 = __shfl_sync(0xffffffffu, hn, 7);

            if (lane < HID) hbuf[t * HID + lane] = hn;
            xp = xpn;
        }
    }
    __syncthreads();

    // ---- Phase 5a: fc_out, warp w handles t = w, w+16 — pure smem ----
    for (int t = warp; t < TT; t += NWARP) {
        float acc1 = sbo[lane];
        float acc2 = (lane < VV - 32) ? sbo[32 + lane] : 0.0f;
        #pragma unroll
        for (int j = 0; j < HID; ++j) {
            float hv = hbuf[t * HID + j];
            acc1 = fmaf(hv, sWout[lane * 9 + j], acc1);
            if (lane < VV - 32)
                acc2 = fmaf(hv, sWout[(32 + lane) * 9 + j], acc2);
        }
        logits[t * VV + lane] = acc1;
        if (lane < VV - 32) logits[t * VV + 32 + lane] = acc2;
    }
    __syncthreads();

    // ---- Phase 5b: parallel softmax over TIME + fused store ----
    {
        const int sg = lane >> 3;            // 0..3
        const int sl = lane & 7;             // t = sl, sl+8, sl+16, sl+24
        const int v  = warp * 4 + sg;        // 0..63; valid if < VV
        const int vc = (v < VV) ? v : 0;

        float x0 = logits[(sl     ) * VV + vc];
        float x1 = logits[(sl +  8) * VV + vc];
        float x2 = logits[(sl + 16) * VV + vc];
        float x3 = logits[(sl + 24) * VV + vc];

        float m = fmaxf(fmaxf(x0, x1), fmaxf(x2, x3));
        #pragma unroll
        for (int o = 4; o > 0; o >>= 1)
            m = fmaxf(m, __shfl_xor_sync(0xffffffffu, m, o, 8));

        float e0 = __expf(x0 - m);
        float e1 = __expf(x1 - m);
        float e2 = __expf(x2 - m);
        float e3 = __expf(x3 - m);
        float s = (e0 + e1) + (e2 + e3);
        #pragma unroll
        for (int o = 4; o > 0; o >>= 1)
            s += __shfl_xor_sync(0xffffffffu, s, o, 8);
        float r = 1.0f / s;

        if (v < VV) {
            float* ob = out + (size_t)b * TT * VV + v;
            ob[(sl     ) * VV] = e0 * r;
            ob[(sl +  8) * VV] = e1 * r;
            ob[(sl + 16) * VV] = e2 * r;
            ob[(sl + 24) * VV] = e3 * r;
        }
    }
}

// ---------------------------------------------------------------------------
extern "C" void kernel_launch(void* const* d_in, const int* in_sizes, int n_in,
                              void* d_out, int out_size)
{
    const float* features = (const float*)d_in[0];
    const float* captions = (const float*)d_in[1];
    const float* W_ih     = (const float*)d_in[2];
    const float* b_ih     = (const float*)d_in[3];
    const float* W_hh     = (const float*)d_in[4];
    const float* b_hh     = (const float*)d_in[5];
    const float* W_in     = (const float*)d_in[6];
    const float* b_in     = (const float*)d_in[7];
    const float* W_out    = (const float*)d_in[8];
    const float* b_out    = (const float*)d_in[9];
    float* out = (float*)d_out;

    lstm_fused_kernel<<<BB, NTHR>>>(features, captions, W_ih, b_ih, W_hh, b_hh,
                                    W_in, b_in, W_out, b_out, out);
    (void)in_sizes; (void)n_in; (void)out_size;
}